// round 10
// baseline (speedup 1.0000x reference)
#include <cuda_runtime.h>
#include <cuda_bf16.h>
#include <cstdint>
#include <cstddef>

// Problem constants
#define Bg    16
#define Ntok  512
#define Eg    131072
#define MROWS (Bg * Ntok)          // 8192
#define SCALE 0.17677669529663687f // 1/sqrt(32)

// Scratch (device globals; no allocation allowed)
__device__ float    g_q[MROWS * 256];
__device__ float    g_k[MROWS * 256];
__device__ float    g_v[MROWS * 256];
__device__ float    g_att[MROWS * 256];
__device__ unsigned g_mask[Bg * Ntok * 16];  // 131072 words
// Transposed + hi/lo-split weights: [4 weights][N=256 rows][K=256 cols] K-major
__device__ __align__(16) __nv_bfloat16 g_wt_hi[4 * 256 * 256];
__device__ __align__(16) __nv_bfloat16 g_wt_lo[4 * 256 * 256];

// ---------------------------------------------------------------------------
// Warp-MMA helpers (portable sm_80+ path; harness PTX target is compute_100
// without 'a' suffix -> tcgen05 unavailable)
// ---------------------------------------------------------------------------
__device__ __forceinline__ void ldsm_x4(uint32_t addr, uint32_t* r) {
    asm volatile("ldmatrix.sync.aligned.m8n8.x4.shared.b16 {%0,%1,%2,%3}, [%4];"
                 : "=r"(r[0]), "=r"(r[1]), "=r"(r[2]), "=r"(r[3]) : "r"(addr));
}
__device__ __forceinline__ void ldsm_x2(uint32_t addr, uint32_t* r) {
    asm volatile("ldmatrix.sync.aligned.m8n8.x2.shared.b16 {%0,%1}, [%2];"
                 : "=r"(r[0]), "=r"(r[1]) : "r"(addr));
}
__device__ __forceinline__ void mma_bf16(float* c, const uint32_t* a, const uint32_t* b) {
    asm volatile(
        "mma.sync.aligned.m16n8k16.row.col.f32.bf16.bf16.f32 "
        "{%0,%1,%2,%3}, {%4,%5,%6,%7}, {%8,%9}, {%0,%1,%2,%3};"
        : "+f"(c[0]), "+f"(c[1]), "+f"(c[2]), "+f"(c[3])
        : "r"(a[0]), "r"(a[1]), "r"(a[2]), "r"(a[3]), "r"(b[0]), "r"(b[1]));
}
__device__ __forceinline__ uint32_t pack_bf2(__nv_bfloat16 a, __nv_bfloat16 b) {
    __nv_bfloat162 t(a, b);
    return *reinterpret_cast<uint32_t*>(&t);
}

// ---------------------------------------------------------------------------
// Weight prep: W[K=256][N=256] fp32 -> Wt_hi/Wt_lo[N][K] bf16 (transpose+split)
// ---------------------------------------------------------------------------
__global__ void wsplit_kernel(const float* __restrict__ Wq, const float* __restrict__ Wk,
                              const float* __restrict__ Wv, const float* __restrict__ Wo,
                              __nv_bfloat16* __restrict__ wt_hi,
                              __nv_bfloat16* __restrict__ wt_lo) {
    const float* W = (blockIdx.z == 0) ? Wq : (blockIdx.z == 1) ? Wk
                   : (blockIdx.z == 2) ? Wv : Wo;
    __shared__ float tile[32][33];
    int tx = threadIdx.x, ty = threadIdx.y;
    int n0 = blockIdx.x * 32, k0 = blockIdx.y * 32;
#pragma unroll
    for (int j = 0; j < 4; j++)
        tile[ty + 8 * j][tx] = W[(k0 + ty + 8 * j) * 256 + n0 + tx];
    __syncthreads();
    size_t wbase = (size_t)blockIdx.z * 65536;
#pragma unroll
    for (int j = 0; j < 4; j++) {
        int n = n0 + ty + 8 * j;
        int k = k0 + tx;
        float x = tile[tx][ty + 8 * j];
        __nv_bfloat16 hi = __float2bfloat16(x);
        __nv_bfloat16 lo = __float2bfloat16(x - __bfloat162float(hi));
        wt_hi[wbase + (size_t)n * 256 + k] = hi;
        wt_lo[wbase + (size_t)n * 256 + k] = lo;
    }
}

// ---------------------------------------------------------------------------
// Mask build: diag (self loops) + edge scatter
// ---------------------------------------------------------------------------
__global__ void mask_init_kernel(unsigned* __restrict__ mask) {
    int idx = blockIdx.x * 256 + threadIdx.x;
    int w = idx & 15;
    int r = (idx >> 4) & 511;
    mask[idx] = ((r >> 5) == w) ? (1u << (r & 31)) : 0u;
}

__global__ void mask_edges_kernel(const int* __restrict__ src,
                                  const int* __restrict__ dst,
                                  unsigned* __restrict__ mask) {
    int i = blockIdx.x * 256 + threadIdx.x;
    int s = src[i];
    int d = dst[i];
    int b = s >> 9;
    int r = s & 511;
    int c = d & 511;
    atomicOr(&mask[((b << 9) + r) * 16 + (c >> 5)], 1u << (c & 31));
}

// ---------------------------------------------------------------------------
// bf16 hi/lo split GEMM (R6 config verbatim -- best measured at 95.7us).
// C[128,128] = A[128,256] @ Wt^T + bias per block. 3-term Markidis.
// 512 threads = 16 warps (4m x 4n), warp tile 32x32, m16n8k16 mma.sync.
// ---------------------------------------------------------------------------
#define KCH   32
#define NCHNK 8
#define ASTR  40                 // smem row stride in halfs

struct Pf {
    float4 a[2];
    uint4  bh, bl;
};

__device__ __forceinline__ void pf_load(Pf& p, const float* __restrict__ A,
                                        const __nv_bfloat16* __restrict__ wth,
                                        const __nv_bfloat16* __restrict__ wtl,
                                        int row0, int col0, int ch, int tid) {
#pragma unroll
    for (int i = 0; i < 2; i++) {
        int idx = tid + i * 512;
        int r = idx >> 3, f4 = idx & 7;
        p.a[i] = *reinterpret_cast<const float4*>(
            A + (size_t)(row0 + r) * 256 + ch * KCH + f4 * 4);
    }
    int r = tid >> 2, q = tid & 3;
    p.bh = *reinterpret_cast<const uint4*>(wth + (size_t)(col0 + r) * 256 + ch * KCH + q * 8);
    p.bl = *reinterpret_cast<const uint4*>(wtl + (size_t)(col0 + r) * 256 + ch * KCH + q * 8);
}

__device__ __forceinline__ void pf_store(const Pf& p,
                                         __nv_bfloat16* Ash, __nv_bfloat16* Asl,
                                         __nv_bfloat16* Bsh, __nv_bfloat16* Bsl,
                                         int tid) {
#pragma unroll
    for (int i = 0; i < 2; i++) {
        int idx = tid + i * 512;
        int r = idx >> 3, f4 = idx & 7;
        float4 va = p.a[i];
        __nv_bfloat16 h0 = __float2bfloat16(va.x), h1 = __float2bfloat16(va.y);
        __nv_bfloat16 h2 = __float2bfloat16(va.z), h3 = __float2bfloat16(va.w);
        __nv_bfloat16 l0 = __float2bfloat16(va.x - __bfloat162float(h0));
        __nv_bfloat16 l1 = __float2bfloat16(va.y - __bfloat162float(h1));
        __nv_bfloat16 l2 = __float2bfloat16(va.z - __bfloat162float(h2));
        __nv_bfloat16 l3 = __float2bfloat16(va.w - __bfloat162float(h3));
        uint2 sh, sl;
        sh.x = pack_bf2(h0, h1); sh.y = pack_bf2(h2, h3);
        sl.x = pack_bf2(l0, l1); sl.y = pack_bf2(l2, l3);
        *reinterpret_cast<uint2*>(&Ash[r * ASTR + f4 * 4]) = sh;
        *reinterpret_cast<uint2*>(&Asl[r * ASTR + f4 * 4]) = sl;
    }
    int r = tid >> 2, q = tid & 3;
    *reinterpret_cast<uint4*>(&Bsh[r * ASTR + q * 8]) = p.bh;
    *reinterpret_cast<uint4*>(&Bsl[r * ASTR + q * 8]) = p.bl;
}

__device__ __forceinline__ void mma_gemm_body(
    const float* __restrict__ A,
    const __nv_bfloat16* __restrict__ wth,
    const __nv_bfloat16* __restrict__ wtl,
    const float* __restrict__ bias,
    float* __restrict__ C, int row0, int col0) {
    __shared__ __align__(16) __nv_bfloat16 Ash[128 * ASTR];
    __shared__ __align__(16) __nv_bfloat16 Asl[128 * ASTR];
    __shared__ __align__(16) __nv_bfloat16 Bsh[128 * ASTR];
    __shared__ __align__(16) __nv_bfloat16 Bsl[128 * ASTR];

    int tid  = threadIdx.x;           // 0..511
    int wid  = tid >> 5;
    int lane = tid & 31;
    int wrow = (wid >> 2) * 32;
    int wn   = (wid & 3) * 32;

    uint32_t ah_b = (uint32_t)__cvta_generic_to_shared(Ash);
    uint32_t al_b = (uint32_t)__cvta_generic_to_shared(Asl);
    uint32_t bh_b = (uint32_t)__cvta_generic_to_shared(Bsh);
    uint32_t bl_b = (uint32_t)__cvta_generic_to_shared(Bsl);

    int arow = wrow + (lane & 15);
    int ac8  = ((lane >> 4) & 1) * 8;
    int brow = wn + (lane & 7);
    int bc8  = ((lane >> 3) & 1) * 8;

    float acc[2][4][4];
#pragma unroll
    for (int mt = 0; mt < 2; mt++)
#pragma unroll
        for (int nt = 0; nt < 4; nt++)
#pragma unroll
            for (int i = 0; i < 4; i++) acc[mt][nt][i] = 0.f;

    Pf pf;
    pf_load(pf, A, wth, wtl, row0, col0, 0, tid);
    pf_store(pf, Ash, Asl, Bsh, Bsl, tid);
    __syncthreads();

#pragma unroll 1
    for (int ch = 0; ch < NCHNK; ch++) {
        if (ch + 1 < NCHNK)
            pf_load(pf, A, wth, wtl, row0, col0, ch + 1, tid);

#pragma unroll
        for (int ks = 0; ks < 2; ks++) {
            uint32_t ah[2][4], al[2][4], bh[4][2], bl[4][2];
#pragma unroll
            for (int mt = 0; mt < 2; mt++) {
                uint32_t off = (uint32_t)(((arow + mt * 16) * ASTR + ks * 16 + ac8) * 2);
                ldsm_x4(ah_b + off, ah[mt]);
                ldsm_x4(al_b + off, al[mt]);
            }
#pragma unroll
            for (int nt = 0; nt < 4; nt++) {
                uint32_t off = (uint32_t)(((brow + nt * 8) * ASTR + ks * 16 + bc8) * 2);
                ldsm_x2(bh_b + off, bh[nt]);
                ldsm_x2(bl_b + off, bl[nt]);
            }
#pragma unroll
            for (int mt = 0; mt < 2; mt++)
#pragma unroll
                for (int nt = 0; nt < 4; nt++) {
                    mma_bf16(acc[mt][nt], ah[mt], bh[nt]);
                    mma_bf16(acc[mt][nt], ah[mt], bl[nt]);
                    mma_bf16(acc[mt][nt], al[mt], bh[nt]);
                }
        }
        __syncthreads();
        if (ch + 1 < NCHNK) {
            pf_store(pf, Ash, Asl, Bsh, Bsl, tid);
            __syncthreads();
        }
    }

    // Epilogue
#pragma unroll
    for (int mt = 0; mt < 2; mt++) {
#pragma unroll
        for (int nt = 0; nt < 4; nt++) {
            int r = row0 + wrow + mt * 16 + (lane >> 2);
            int c = col0 + wn + nt * 8 + (lane & 3) * 2;
            float b0 = bias[c], b1 = bias[c + 1];
            float2 o0 = make_float2(acc[mt][nt][0] + b0, acc[mt][nt][1] + b1);
            float2 o1 = make_float2(acc[mt][nt][2] + b0, acc[mt][nt][3] + b1);
            *reinterpret_cast<float2*>(C + (size_t)r * 256 + c)       = o0;
            *reinterpret_cast<float2*>(C + (size_t)(r + 8) * 256 + c) = o1;
        }
    }
}

__global__ __launch_bounds__(512, 1) void mma_qkv_kernel(
    const float* __restrict__ A,
    const __nv_bfloat16* __restrict__ wt_hi, const __nv_bfloat16* __restrict__ wt_lo,
    const float* bq, const float* bk, const float* bv,
    float* q, float* k, float* v) {
    int wsel = blockIdx.z;
    const float* bias = (wsel == 0) ? bq : (wsel == 1) ? bk : bv;
    float* C = (wsel == 0) ? q : (wsel == 1) ? k : v;
    mma_gemm_body(A, wt_hi + (size_t)wsel * 65536, wt_lo + (size_t)wsel * 65536,
                  bias, C, blockIdx.x * 128, blockIdx.y * 128);
}

__global__ __launch_bounds__(512, 1) void mma_o_kernel(
    const float* __restrict__ A,
    const __nv_bfloat16* __restrict__ wt_hi, const __nv_bfloat16* __restrict__ wt_lo,
    const float* __restrict__ bias, float* __restrict__ C) {
    mma_gemm_body(A, wt_hi + (size_t)3 * 65536, wt_lo + (size_t)3 * 65536,
                  bias, C, blockIdx.x * 128, blockIdx.y * 128);
}

// ---------------------------------------------------------------------------
// Sparse masked attention, restructured for memory-level parallelism.
// Warp per (b,q); lane = (head h = lane>>2, sub = lane&3), lane owns 8 dims.
// Per chunk of <=64 edges:
//   decode -> edge list in smem (warp-parallel popc + prefix)
//   score pass:  independent iterations (k loads pipeline via MLP)
//   reduce:      per-head chunk max / sum (smem scores, 2 shuffles)
//   value pass:  independent iterations (v loads pipeline via MLP)
// Chunk-wise online softmax across chunks; exp underflow of masked keys makes
// this numerically identical to the dense reference.
// ---------------------------------------------------------------------------
#define SSTR 65   // per-head score stride in smem (65 mod 32 = 1 -> no conflicts)

__global__ __launch_bounds__(256) void attn_kernel(
    const float* __restrict__ q, const float* __restrict__ k,
    const float* __restrict__ v, const unsigned* __restrict__ mask,
    float* __restrict__ att) {
    __shared__ unsigned short js_s[8][512];
    __shared__ float ss_s[8][8 * SSTR];

    int wslot = threadIdx.x >> 5;
    int gw   = blockIdx.x * 8 + wslot;   // global (b,q) id, < 8192
    int lane = threadIdx.x & 31;
    int qi = gw & 511;
    int b  = gw >> 9;
    int h   = lane >> 2;
    int sub = lane & 3;
    unsigned short* js = js_s[wslot];
    float* ssw = ss_s[wslot] + h * SSTR;

    // --- decode mask row into edge list (ascending j) ---
    const unsigned* mrow = mask + ((b << 9) + qi) * 16;
    unsigned bits = (lane < 16) ? mrow[lane] : 0u;
    int cnt = __popc(bits);
    int pre = cnt;
#pragma unroll
    for (int o = 1; o < 32; o <<= 1) {
        int t = __shfl_up_sync(0xffffffffu, pre, o);
        if (lane >= o) pre += t;
    }
    int deg = __shfl_sync(0xffffffffu, pre, 31);
    pre -= cnt;
    unsigned bb = bits;
    int p = pre;
    while (bb) {
        int bit = __ffs(bb) - 1;
        bb &= bb - 1;
        js[p++] = (unsigned short)((lane << 5) + bit);
    }
    __syncwarp();

    int off = lane * 8;
    size_t qrow = (size_t)gw * 256;
    float4 qa = *reinterpret_cast<const float4*>(q + qrow + off);
    float4 qb = *reinterpret_cast<const float4*>(q + qrow + off + 4);
    size_t bbase = (size_t)(b << 9) * 256;

    float m = -1e30f, l = 0.f;
    float acc[8];
#pragma unroll
    for (int d = 0; d < 8; d++) acc[d] = 0.f;

#pragma unroll 1
    for (int e0 = 0; e0 < deg; e0 += 64) {
        int ne = min(64, deg - e0);

        // --- score pass: independent iterations ---
#pragma unroll 2
        for (int e = 0; e < ne; e++) {
            int j = js[e0 + e];
            const float* krow = k + bbase + (size_t)j * 256 + off;
            float4 ka = *reinterpret_cast<const float4*>(krow);
            float4 kb = *reinterpret_cast<const float4*>(krow + 4);
            float s = qa.x * ka.x + qa.y * ka.y + qa.z * ka.z + qa.w * ka.w
                    + qb.x * kb.x + qb.y * kb.y + qb.z * kb.z + qb.w * kb.w;
            s += __shfl_xor_sync(0xffffffffu, s, 1);
            s += __shfl_xor_sync(0xffffffffu, s, 2);
            if (sub == (e & 3)) ssw[e] = s * SCALE;
        }
        __syncwarp();

        // --- per-head chunk max & sum ---
        float mc = -1e30f;
        for (int e = sub; e < ne; e += 4) mc = fmaxf(mc, ssw[e]);
        mc = fmaxf(mc, __shfl_xor_sync(0xffffffffu, mc, 1));
        mc = fmaxf(mc, __shfl_xor_sync(0xffffffffu, mc, 2));
        float mn   = fmaxf(m, mc);
        float corr = __expf(m - mn);
        float lc = 0.f;
        for (int e = sub; e < ne; e += 4) lc += __expf(ssw[e] - mn);
        lc += __shfl_xor_sync(0xffffffffu, lc, 1);
        lc += __shfl_xor_sync(0xffffffffu, lc, 2);
        l = l * corr + lc;
#pragma unroll
        for (int d = 0; d < 8; d++) acc[d] *= corr;
        m = mn;

        // --- value pass: independent iterations ---
#pragma unroll 2
        for (int e = 0; e < ne; e++) {
            int j = js[e0 + e];
            const float* vrow = v + bbase + (size_t)j * 256 + off;
            float4 va = *reinterpret_cast<const float4*>(vrow);
            float4 vb = *reinterpret_cast<const float4*>(vrow + 4);
            float pw = __expf(ssw[e] - mn);
            acc[0] += pw * va.x; acc[1] += pw * va.y;
            acc[2] += pw * va.z; acc[3] += pw * va.w;
            acc[4] += pw * vb.x; acc[5] += pw * vb.y;
            acc[6] += pw * vb.z; acc[7] += pw * vb.w;
        }
        __syncwarp();
    }

    float inv = 1.f / l;
    float4 oa, ob;
    oa.x = acc[0] * inv; oa.y = acc[1] * inv; oa.z = acc[2] * inv; oa.w = acc[3] * inv;
    ob.x = acc[4] * inv; ob.y = acc[5] * inv; ob.z = acc[6] * inv; ob.w = acc[7] * inv;
    *reinterpret_cast<float4*>(att + qrow + off)     = oa;
    *reinterpret_cast<float4*>(att + qrow + off + 4) = ob;
}

// ---------------------------------------------------------------------------
// Launch
// ---------------------------------------------------------------------------
extern "C" void kernel_launch(void* const* d_in, const int* in_sizes, int n_in,
                              void* d_out, int out_size) {
    const float* h   = (const float*)d_in[0];
    const int*   src = (const int*)d_in[1];
    const int*   dst = (const int*)d_in[2];
    const float* Wq  = (const float*)d_in[3];
    const float* bq  = (const float*)d_in[4];
    const float* Wk  = (const float*)d_in[5];
    const float* bk  = (const float*)d_in[6];
    const float* Wv  = (const float*)d_in[7];
    const float* bv  = (const float*)d_in[8];
    const float* Wo  = (const float*)d_in[9];
    const float* bo  = (const float*)d_in[10];
    float* out = (float*)d_out;

    float *pq, *pk, *pv, *patt;
    unsigned* pmask;
    __nv_bfloat16 *pwh, *pwl;
    cudaGetSymbolAddress((void**)&pq,    g_q);
    cudaGetSymbolAddress((void**)&pk,    g_k);
    cudaGetSymbolAddress((void**)&pv,    g_v);
    cudaGetSymbolAddress((void**)&patt,  g_att);
    cudaGetSymbolAddress((void**)&pmask, g_mask);
    cudaGetSymbolAddress((void**)&pwh,   g_wt_hi);
    cudaGetSymbolAddress((void**)&pwl,   g_wt_lo);

    // Weight transpose + hi/lo split; mask build (all independent)
    wsplit_kernel<<<dim3(8, 8, 4), dim3(32, 8)>>>(Wq, Wk, Wv, Wo, pwh, pwl);
    mask_init_kernel<<<Bg * Ntok * 16 / 256, 256>>>(pmask);
    mask_edges_kernel<<<Eg / 256, 256>>>(src, dst, pmask);

    // Q/K/V projections via mma.sync bf16 split (R6 config)
    mma_qkv_kernel<<<dim3(MROWS / 128, 2, 3), 512>>>(
        h, pwh, pwl, bq, bk, bv, pq, pk, pv);

    // Sparse masked attention (pipelined two-pass per chunk)
    attn_kernel<<<MROWS / 8, 256>>>(pq, pk, pv, pmask, patt);

    // Output projection straight into d_out
    mma_o_kernel<<<dim3(MROWS / 128, 2), 512>>>(patt, pwh, pwl, bo, out);
}

// round 11
// speedup vs baseline: 1.4628x; 1.4628x over previous
#include <cuda_runtime.h>
#include <cuda_fp16.h>
#include <cstdint>
#include <cstddef>

// Problem constants
#define Bg    16
#define Ntok  512
#define Eg    131072
#define MROWS (Bg * Ntok)          // 8192
#define SCALE 0.17677669529663687f // 1/sqrt(32)

// Scratch (device globals; no allocation allowed)
__device__ float    g_q[MROWS * 256];
__device__ float    g_k[MROWS * 256];
__device__ float    g_v[MROWS * 256];
__device__ float    g_att[MROWS * 256];
__device__ unsigned g_mask[Bg * Ntok * 16];  // 131072 words
// Transposed fp16 weights: [4 weights][N=256 rows][K=256 cols] K-major
__device__ __align__(16) __half g_wt[4 * 256 * 256];

// ---------------------------------------------------------------------------
// Warp-MMA helpers (portable sm_80+ path; harness PTX target is compute_100
// without 'a' suffix -> tcgen05 unavailable)
// ---------------------------------------------------------------------------
__device__ __forceinline__ void ldsm_x4(uint32_t addr, uint32_t* r) {
    asm volatile("ldmatrix.sync.aligned.m8n8.x4.shared.b16 {%0,%1,%2,%3}, [%4];"
                 : "=r"(r[0]), "=r"(r[1]), "=r"(r[2]), "=r"(r[3]) : "r"(addr));
}
__device__ __forceinline__ void ldsm_x2(uint32_t addr, uint32_t* r) {
    asm volatile("ldmatrix.sync.aligned.m8n8.x2.shared.b16 {%0,%1}, [%2];"
                 : "=r"(r[0]), "=r"(r[1]) : "r"(addr));
}
__device__ __forceinline__ void mma_f16(float* c, const uint32_t* a, const uint32_t* b) {
    asm volatile(
        "mma.sync.aligned.m16n8k16.row.col.f32.f16.f16.f32 "
        "{%0,%1,%2,%3}, {%4,%5,%6,%7}, {%8,%9}, {%0,%1,%2,%3};"
        : "+f"(c[0]), "+f"(c[1]), "+f"(c[2]), "+f"(c[3])
        : "r"(a[0]), "r"(a[1]), "r"(a[2]), "r"(a[3]), "r"(b[0]), "r"(b[1]));
}
__device__ __forceinline__ uint32_t pack_h2(__half a, __half b) {
    __half2 t(a, b);
    return *reinterpret_cast<uint32_t*>(&t);
}

// ---------------------------------------------------------------------------
// Weight prep: W[K=256][N=256] fp32 -> Wt[N][K] fp16 (transpose + convert)
// ---------------------------------------------------------------------------
__global__ void wconv_kernel(const float* __restrict__ Wq, const float* __restrict__ Wk,
                             const float* __restrict__ Wv, const float* __restrict__ Wo,
                             __half* __restrict__ wt) {
    const float* W = (blockIdx.z == 0) ? Wq : (blockIdx.z == 1) ? Wk
                   : (blockIdx.z == 2) ? Wv : Wo;
    __shared__ float tile[32][33];
    int tx = threadIdx.x, ty = threadIdx.y;
    int n0 = blockIdx.x * 32, k0 = blockIdx.y * 32;
#pragma unroll
    for (int j = 0; j < 4; j++)
        tile[ty + 8 * j][tx] = W[(k0 + ty + 8 * j) * 256 + n0 + tx];
    __syncthreads();
    size_t wbase = (size_t)blockIdx.z * 65536;
#pragma unroll
    for (int j = 0; j < 4; j++) {
        int n = n0 + ty + 8 * j;
        int k = k0 + tx;
        wt[wbase + (size_t)n * 256 + k] = __float2half_rn(tile[tx][ty + 8 * j]);
    }
}

// ---------------------------------------------------------------------------
// Mask build: diag (self loops) + edge scatter
// ---------------------------------------------------------------------------
__global__ void mask_init_kernel(unsigned* __restrict__ mask) {
    int idx = blockIdx.x * 256 + threadIdx.x;
    int w = idx & 15;
    int r = (idx >> 4) & 511;
    mask[idx] = ((r >> 5) == w) ? (1u << (r & 31)) : 0u;
}

__global__ void mask_edges_kernel(const int* __restrict__ src,
                                  const int* __restrict__ dst,
                                  unsigned* __restrict__ mask) {
    int i = blockIdx.x * 256 + threadIdx.x;
    int s = src[i];
    int d = dst[i];
    int b = s >> 9;
    int r = s & 511;
    int c = d & 511;
    atomicOr(&mask[((b << 9) + r) * 16 + (c >> 5)], 1u << (c & 31));
}

// ---------------------------------------------------------------------------
// fp16 single-pass GEMM: C[128,128] = A[128,256] @ Wt^T + bias per block.
// 512 threads = 16 warps (4m x 4n), warp tile 32x32, m16n8k16 mma.sync.
// A fp32 -> fp16 converted in the store stage; weights pre-converted.
// smem row stride 40 halfs (80B) -> ldmatrix phases conflict-free.
// ---------------------------------------------------------------------------
#define KCH   32
#define NCHNK 8
#define ASTR  40                 // smem row stride in halfs

struct Pf {
    float4 a[2];
    uint4  b;
};

__device__ __forceinline__ void pf_load(Pf& p, const float* __restrict__ A,
                                        const __half* __restrict__ wt,
                                        int row0, int col0, int ch, int tid) {
#pragma unroll
    for (int i = 0; i < 2; i++) {
        int idx = tid + i * 512;
        int r = idx >> 3, f4 = idx & 7;
        p.a[i] = *reinterpret_cast<const float4*>(
            A + (size_t)(row0 + r) * 256 + ch * KCH + f4 * 4);
    }
    int r = tid >> 2, q = tid & 3;
    p.b = *reinterpret_cast<const uint4*>(wt + (size_t)(col0 + r) * 256 + ch * KCH + q * 8);
}

__device__ __forceinline__ void pf_store(const Pf& p,
                                         __half* Ash, __half* Bsh, int tid) {
#pragma unroll
    for (int i = 0; i < 2; i++) {
        int idx = tid + i * 512;
        int r = idx >> 3, f4 = idx & 7;
        float4 va = p.a[i];
        uint2 u;
        u.x = pack_h2(__float2half_rn(va.x), __float2half_rn(va.y));
        u.y = pack_h2(__float2half_rn(va.z), __float2half_rn(va.w));
        *reinterpret_cast<uint2*>(&Ash[r * ASTR + f4 * 4]) = u;
    }
    int r = tid >> 2, q = tid & 3;
    *reinterpret_cast<uint4*>(&Bsh[r * ASTR + q * 8]) = p.b;
}

__device__ __forceinline__ void mma_gemm_body(
    const float* __restrict__ A,
    const __half* __restrict__ wt,
    const float* __restrict__ bias,
    float* __restrict__ C, int row0, int col0) {
    __shared__ __align__(16) __half Ash[128 * ASTR];
    __shared__ __align__(16) __half Bsh[128 * ASTR];

    int tid  = threadIdx.x;           // 0..511
    int wid  = tid >> 5;
    int lane = tid & 31;
    int wrow = (wid >> 2) * 32;
    int wn   = (wid & 3) * 32;

    uint32_t a_b = (uint32_t)__cvta_generic_to_shared(Ash);
    uint32_t b_b = (uint32_t)__cvta_generic_to_shared(Bsh);

    int arow = wrow + (lane & 15);
    int ac8  = ((lane >> 4) & 1) * 8;
    int brow = wn + (lane & 7);
    int bc8  = ((lane >> 3) & 1) * 8;

    float acc[2][4][4];
#pragma unroll
    for (int mt = 0; mt < 2; mt++)
#pragma unroll
        for (int nt = 0; nt < 4; nt++)
#pragma unroll
            for (int i = 0; i < 4; i++) acc[mt][nt][i] = 0.f;

    Pf pf;
    pf_load(pf, A, wt, row0, col0, 0, tid);
    pf_store(pf, Ash, Bsh, tid);
    __syncthreads();

#pragma unroll 1
    for (int ch = 0; ch < NCHNK; ch++) {
        if (ch + 1 < NCHNK)
            pf_load(pf, A, wt, row0, col0, ch + 1, tid);

#pragma unroll
        for (int ks = 0; ks < 2; ks++) {
            uint32_t ah[2][4], bh[4][2];
#pragma unroll
            for (int mt = 0; mt < 2; mt++) {
                uint32_t off = (uint32_t)(((arow + mt * 16) * ASTR + ks * 16 + ac8) * 2);
                ldsm_x4(a_b + off, ah[mt]);
            }
#pragma unroll
            for (int nt = 0; nt < 4; nt++) {
                uint32_t off = (uint32_t)(((brow + nt * 8) * ASTR + ks * 16 + bc8) * 2);
                ldsm_x2(b_b + off, bh[nt]);
            }
#pragma unroll
            for (int mt = 0; mt < 2; mt++)
#pragma unroll
                for (int nt = 0; nt < 4; nt++)
                    mma_f16(acc[mt][nt], ah[mt], bh[nt]);
        }
        __syncthreads();
        if (ch + 1 < NCHNK) {
            pf_store(pf, Ash, Bsh, tid);
            __syncthreads();
        }
    }

    // Epilogue
#pragma unroll
    for (int mt = 0; mt < 2; mt++) {
#pragma unroll
        for (int nt = 0; nt < 4; nt++) {
            int r = row0 + wrow + mt * 16 + (lane >> 2);
            int c = col0 + wn + nt * 8 + (lane & 3) * 2;
            float b0 = bias[c], b1 = bias[c + 1];
            float2 o0 = make_float2(acc[mt][nt][0] + b0, acc[mt][nt][1] + b1);
            float2 o1 = make_float2(acc[mt][nt][2] + b0, acc[mt][nt][3] + b1);
            *reinterpret_cast<float2*>(C + (size_t)r * 256 + c)       = o0;
            *reinterpret_cast<float2*>(C + (size_t)(r + 8) * 256 + c) = o1;
        }
    }
}

__global__ __launch_bounds__(512, 1) void mma_qkv_kernel(
    const float* __restrict__ A, const __half* __restrict__ wt,
    const float* bq, const float* bk, const float* bv,
    float* q, float* k, float* v) {
    int wsel = blockIdx.z;
    const float* bias = (wsel == 0) ? bq : (wsel == 1) ? bk : bv;
    float* C = (wsel == 0) ? q : (wsel == 1) ? k : v;
    mma_gemm_body(A, wt + (size_t)wsel * 65536, bias, C,
                  blockIdx.x * 128, blockIdx.y * 128);
}

__global__ __launch_bounds__(512, 1) void mma_o_kernel(
    const float* __restrict__ A, const __half* __restrict__ wt,
    const float* __restrict__ bias, float* __restrict__ C) {
    mma_gemm_body(A, wt + (size_t)3 * 65536, bias, C,
                  blockIdx.x * 128, blockIdx.y * 128);
}

// ---------------------------------------------------------------------------
// Sparse masked attention (R4 version verbatim -- measured 31.9us).
// Warp per (b,q), all 8 heads; lane owns 8 dims. Masked keys contribute
// exactly 0 (exp underflow) -> identical to the dense reference.
// ---------------------------------------------------------------------------
__global__ __launch_bounds__(256) void attn_kernel(
    const float* __restrict__ q, const float* __restrict__ k,
    const float* __restrict__ v, const unsigned* __restrict__ mask,
    float* __restrict__ att) {
    int gw   = blockIdx.x * 8 + (threadIdx.x >> 5);
    int lane = threadIdx.x & 31;
    int qi = gw & 511;
    int b  = gw >> 9;

    int off = lane * 8;
    size_t qrow = (size_t)gw * 256;
    float4 qa = *reinterpret_cast<const float4*>(q + qrow + off);
    float4 qb = *reinterpret_cast<const float4*>(q + qrow + off + 4);

    float m = -1e30f, l = 0.f;
    float acc[8];
#pragma unroll
    for (int d = 0; d < 8; d++) acc[d] = 0.f;

    const unsigned* mrow = mask + ((b << 9) + qi) * 16;
    size_t bbase = (size_t)(b << 9) * 256;

#pragma unroll 1
    for (int w = 0; w < 16; w++) {
        unsigned bits = mrow[w];
        while (bits) {
            int bit = __ffs(bits) - 1;
            bits &= bits - 1;
            int j = (w << 5) + bit;
            const float* krow = k + bbase + (size_t)j * 256 + off;
            const float* vrow = v + bbase + (size_t)j * 256 + off;
            float4 ka = *reinterpret_cast<const float4*>(krow);
            float4 kb = *reinterpret_cast<const float4*>(krow + 4);
            float4 va = *reinterpret_cast<const float4*>(vrow);
            float4 vb = *reinterpret_cast<const float4*>(vrow + 4);

            float s = qa.x * ka.x + qa.y * ka.y + qa.z * ka.z + qa.w * ka.w
                    + qb.x * kb.x + qb.y * kb.y + qb.z * kb.z + qb.w * kb.w;
            s += __shfl_xor_sync(0xffffffffu, s, 1);
            s += __shfl_xor_sync(0xffffffffu, s, 2);
            s *= SCALE;

            float mn   = fmaxf(m, s);
            float corr = __expf(m - mn);
            float p    = __expf(s - mn);
            l = l * corr + p;
            m = mn;
            acc[0] = acc[0] * corr + p * va.x;
            acc[1] = acc[1] * corr + p * va.y;
            acc[2] = acc[2] * corr + p * va.z;
            acc[3] = acc[3] * corr + p * va.w;
            acc[4] = acc[4] * corr + p * vb.x;
            acc[5] = acc[5] * corr + p * vb.y;
            acc[6] = acc[6] * corr + p * vb.z;
            acc[7] = acc[7] * corr + p * vb.w;
        }
    }

    float inv = 1.f / l;
    float4 oa, ob;
    oa.x = acc[0] * inv; oa.y = acc[1] * inv; oa.z = acc[2] * inv; oa.w = acc[3] * inv;
    ob.x = acc[4] * inv; ob.y = acc[5] * inv; ob.z = acc[6] * inv; ob.w = acc[7] * inv;
    *reinterpret_cast<float4*>(att + qrow + off)     = oa;
    *reinterpret_cast<float4*>(att + qrow + off + 4) = ob;
}

// ---------------------------------------------------------------------------
// Launch
// ---------------------------------------------------------------------------
extern "C" void kernel_launch(void* const* d_in, const int* in_sizes, int n_in,
                              void* d_out, int out_size) {
    const float* h   = (const float*)d_in[0];
    const int*   src = (const int*)d_in[1];
    const int*   dst = (const int*)d_in[2];
    const float* Wq  = (const float*)d_in[3];
    const float* bq  = (const float*)d_in[4];
    const float* Wk  = (const float*)d_in[5];
    const float* bk  = (const float*)d_in[6];
    const float* Wv  = (const float*)d_in[7];
    const float* bv  = (const float*)d_in[8];
    const float* Wo  = (const float*)d_in[9];
    const float* bo  = (const float*)d_in[10];
    float* out = (float*)d_out;

    float *pq, *pk, *pv, *patt;
    unsigned* pmask;
    __half* pwt;
    cudaGetSymbolAddress((void**)&pq,    g_q);
    cudaGetSymbolAddress((void**)&pk,    g_k);
    cudaGetSymbolAddress((void**)&pv,    g_v);
    cudaGetSymbolAddress((void**)&patt,  g_att);
    cudaGetSymbolAddress((void**)&pmask, g_mask);
    cudaGetSymbolAddress((void**)&pwt,   g_wt);

    // Weight transpose + fp16 convert; mask build (all independent)
    wconv_kernel<<<dim3(8, 8, 4), dim3(32, 8)>>>(Wq, Wk, Wv, Wo, pwt);
    mask_init_kernel<<<Bg * Ntok * 16 / 256, 256>>>(pmask);
    mask_edges_kernel<<<Eg / 256, 256>>>(src, dst, pmask);

    // Q/K/V projections via fp16 single-pass mma.sync
    mma_qkv_kernel<<<dim3(MROWS / 128, 2, 3), 512>>>(
        h, pwt, bq, bk, bv, pq, pk, pv);

    // Sparse masked attention
    attn_kernel<<<MROWS / 8, 256>>>(pq, pk, pv, pmask, patt);

    // Output projection straight into d_out
    mma_o_kernel<<<dim3(MROWS / 128, 2), 512>>>(patt, pwt, bo, out);
}

// round 13
// speedup vs baseline: 1.5438x; 1.0554x over previous
#include <cuda_runtime.h>
#include <cuda_fp16.h>
#include <cstdint>
#include <cstddef>

// Problem constants
#define Bg    16
#define Ntok  512
#define Eg    131072
#define MROWS (Bg * Ntok)          // 8192
#define SCALE 0.17677669529663687f // 1/sqrt(32)

// Scratch (device globals; no allocation allowed)
__device__ float    g_q[MROWS * 256];
__device__ __align__(16) __half g_k16[MROWS * 256];
__device__ __align__(16) __half g_v16[MROWS * 256];
__device__ float    g_att[MROWS * 256];
__device__ unsigned g_mask[Bg * Ntok * 16];  // 131072 words
// Transposed fp16 weights: [4 weights][N=256 rows][K=256 cols] K-major
__device__ __align__(16) __half g_wt[4 * 256 * 256];

// ---------------------------------------------------------------------------
// Warp-MMA helpers (portable sm_80+ path; harness PTX target is compute_100
// without 'a' suffix -> tcgen05 unavailable)
// ---------------------------------------------------------------------------
__device__ __forceinline__ void ldsm_x4(uint32_t addr, uint32_t* r) {
    asm volatile("ldmatrix.sync.aligned.m8n8.x4.shared.b16 {%0,%1,%2,%3}, [%4];"
                 : "=r"(r[0]), "=r"(r[1]), "=r"(r[2]), "=r"(r[3]) : "r"(addr));
}
__device__ __forceinline__ void ldsm_x2(uint32_t addr, uint32_t* r) {
    asm volatile("ldmatrix.sync.aligned.m8n8.x2.shared.b16 {%0,%1}, [%2];"
                 : "=r"(r[0]), "=r"(r[1]) : "r"(addr));
}
__device__ __forceinline__ void mma_f16(float* c, const uint32_t* a, const uint32_t* b) {
    asm volatile(
        "mma.sync.aligned.m16n8k16.row.col.f32.f16.f16.f32 "
        "{%0,%1,%2,%3}, {%4,%5,%6,%7}, {%8,%9}, {%0,%1,%2,%3};"
        : "+f"(c[0]), "+f"(c[1]), "+f"(c[2]), "+f"(c[3])
        : "r"(a[0]), "r"(a[1]), "r"(a[2]), "r"(a[3]), "r"(b[0]), "r"(b[1]));
}
__device__ __forceinline__ uint32_t pack_h2(__half a, __half b) {
    __half2 t(a, b);
    return *reinterpret_cast<uint32_t*>(&t);
}

// ---------------------------------------------------------------------------
// Weight prep: W[K=256][N=256] fp32 -> Wt[N][K] fp16 (transpose + convert)
// ---------------------------------------------------------------------------
__global__ void wconv_kernel(const float* __restrict__ Wq, const float* __restrict__ Wk,
                             const float* __restrict__ Wv, const float* __restrict__ Wo,
                             __half* __restrict__ wt) {
    const float* W = (blockIdx.z == 0) ? Wq : (blockIdx.z == 1) ? Wk
                   : (blockIdx.z == 2) ? Wv : Wo;
    __shared__ float tile[32][33];
    int tx = threadIdx.x, ty = threadIdx.y;
    int n0 = blockIdx.x * 32, k0 = blockIdx.y * 32;
#pragma unroll
    for (int j = 0; j < 4; j++)
        tile[ty + 8 * j][tx] = W[(k0 + ty + 8 * j) * 256 + n0 + tx];
    __syncthreads();
    size_t wbase = (size_t)blockIdx.z * 65536;
#pragma unroll
    for (int j = 0; j < 4; j++) {
        int n = n0 + ty + 8 * j;
        int k = k0 + tx;
        wt[wbase + (size_t)n * 256 + k] = __float2half_rn(tile[tx][ty + 8 * j]);
    }
}

// ---------------------------------------------------------------------------
// Mask build: diag (self loops) + edge scatter
// ---------------------------------------------------------------------------
__global__ void mask_init_kernel(unsigned* __restrict__ mask) {
    int idx = blockIdx.x * 256 + threadIdx.x;
    int w = idx & 15;
    int r = (idx >> 4) & 511;
    mask[idx] = ((r >> 5) == w) ? (1u << (r & 31)) : 0u;
}

__global__ void mask_edges_kernel(const int* __restrict__ src,
                                  const int* __restrict__ dst,
                                  unsigned* __restrict__ mask) {
    int i = blockIdx.x * 256 + threadIdx.x;
    int s = src[i];
    int d = dst[i];
    int b = s >> 9;
    int r = s & 511;
    int c = d & 511;
    atomicOr(&mask[((b << 9) + r) * 16 + (c >> 5)], 1u << (c & 31));
}

// ---------------------------------------------------------------------------
// fp16 single-pass GEMM: C[128,64] per CTA = A[128,256] @ Wt^T + bias.
// 256 threads = 8 warps (4m x 2n), warp tile 32x32, m16n8k16 mma.sync.
// Double-buffered smem, ONE __syncthreads per K-chunk; __launch_bounds(256,2)
// gives 2 CTAs/SM so barrier bubbles are hidden by the co-resident CTA.
// Output: fp32 (C16 == nullptr) or fp16 (k/v for the attention kernel).
// ---------------------------------------------------------------------------
#define KCH   32
#define NCHNK 8
#define ASTR  40                 // smem row stride in halfs (80 B)

struct Pf {
    float4 a[4];
    uint4  b;
};

__device__ __forceinline__ void pf_load(Pf& p, const float* __restrict__ A,
                                        const __half* __restrict__ wt,
                                        int row0, int col0, int ch, int tid) {
#pragma unroll
    for (int i = 0; i < 4; i++) {
        int idx = tid + i * 256;              // 0..1023 float4s
        int r = idx >> 3, f4 = idx & 7;
        p.a[i] = *reinterpret_cast<const float4*>(
            A + (size_t)(row0 + r) * 256 + ch * KCH + f4 * 4);
    }
    int r = tid >> 2, q = tid & 3;            // B: 64 rows x 4 uint4/row
    p.b = *reinterpret_cast<const uint4*>(wt + (size_t)(col0 + r) * 256 + ch * KCH + q * 8);
}

__device__ __forceinline__ void pf_store(const Pf& p,
                                         __half* Ash, __half* Bsh, int tid) {
#pragma unroll
    for (int i = 0; i < 4; i++) {
        int idx = tid + i * 256;
        int r = idx >> 3, f4 = idx & 7;
        float4 va = p.a[i];
        uint2 u;
        u.x = pack_h2(__float2half_rn(va.x), __float2half_rn(va.y));
        u.y = pack_h2(__float2half_rn(va.z), __float2half_rn(va.w));
        *reinterpret_cast<uint2*>(&Ash[r * ASTR + f4 * 4]) = u;
    }
    int r = tid >> 2, q = tid & 3;
    *reinterpret_cast<uint4*>(&Bsh[r * ASTR + q * 8]) = p.b;
}

__device__ __forceinline__ void mma_gemm_body(
    const float* __restrict__ A,
    const __half* __restrict__ wt,
    const float* __restrict__ bias,
    float* __restrict__ C32, __half* __restrict__ C16,
    int row0, int col0) {
    __shared__ __align__(16) __half Ash[2][128 * ASTR];
    __shared__ __align__(16) __half Bsh[2][64 * ASTR];

    int tid  = threadIdx.x;           // 0..255
    int wid  = tid >> 5;              // 0..7
    int lane = tid & 31;
    int wrow = (wid >> 1) * 32;       // 0,32,64,96
    int wn   = (wid & 1) * 32;        // 0,32

    int arow = wrow + (lane & 15);
    int ac8  = ((lane >> 4) & 1) * 8;
    int brow = wn + (lane & 7);
    int bc8  = ((lane >> 3) & 1) * 8;

    float acc[2][4][4];
#pragma unroll
    for (int mt = 0; mt < 2; mt++)
#pragma unroll
        for (int nt = 0; nt < 4; nt++)
#pragma unroll
            for (int i = 0; i < 4; i++) acc[mt][nt][i] = 0.f;

    Pf pf;
    pf_load(pf, A, wt, row0, col0, 0, tid);
    pf_store(pf, Ash[0], Bsh[0], tid);
    __syncthreads();

#pragma unroll 1
    for (int ch = 0; ch < NCHNK; ch++) {
        if (ch + 1 < NCHNK)
            pf_load(pf, A, wt, row0, col0, ch + 1, tid);

        uint32_t a_b = (uint32_t)__cvta_generic_to_shared(Ash[ch & 1]);
        uint32_t b_b = (uint32_t)__cvta_generic_to_shared(Bsh[ch & 1]);
#pragma unroll
        for (int ks = 0; ks < 2; ks++) {
            uint32_t ah[2][4], bh[4][2];
#pragma unroll
            for (int mt = 0; mt < 2; mt++) {
                uint32_t off = (uint32_t)(((arow + mt * 16) * ASTR + ks * 16 + ac8) * 2);
                ldsm_x4(a_b + off, ah[mt]);
            }
#pragma unroll
            for (int nt = 0; nt < 4; nt++) {
                uint32_t off = (uint32_t)(((brow + nt * 8) * ASTR + ks * 16 + bc8) * 2);
                ldsm_x2(b_b + off, bh[nt]);
            }
#pragma unroll
            for (int mt = 0; mt < 2; mt++)
#pragma unroll
                for (int nt = 0; nt < 4; nt++)
                    mma_f16(acc[mt][nt], ah[mt], bh[nt]);
        }
        if (ch + 1 < NCHNK) {
            pf_store(pf, Ash[(ch + 1) & 1], Bsh[(ch + 1) & 1], tid);
            __syncthreads();
        }
    }

    // Epilogue
#pragma unroll
    for (int mt = 0; mt < 2; mt++) {
#pragma unroll
        for (int nt = 0; nt < 4; nt++) {
            int r = row0 + wrow + mt * 16 + (lane >> 2);
            int c = col0 + wn + nt * 8 + (lane & 3) * 2;
            float b0 = bias[c], b1 = bias[c + 1];
            float v00 = acc[mt][nt][0] + b0, v01 = acc[mt][nt][1] + b1;
            float v10 = acc[mt][nt][2] + b0, v11 = acc[mt][nt][3] + b1;
            if (C16) {
                *reinterpret_cast<uint32_t*>(C16 + (size_t)r * 256 + c) =
                    pack_h2(__float2half_rn(v00), __float2half_rn(v01));
                *reinterpret_cast<uint32_t*>(C16 + (size_t)(r + 8) * 256 + c) =
                    pack_h2(__float2half_rn(v10), __float2half_rn(v11));
            } else {
                *reinterpret_cast<float2*>(C32 + (size_t)r * 256 + c) =
                    make_float2(v00, v01);
                *reinterpret_cast<float2*>(C32 + (size_t)(r + 8) * 256 + c) =
                    make_float2(v10, v11);
            }
        }
    }
}

__global__ __launch_bounds__(256, 2) void mma_qkv_kernel(
    const float* __restrict__ A, const __half* __restrict__ wt,
    const float* bq, const float* bk, const float* bv,
    float* q, __half* k16, __half* v16) {
    int wsel = blockIdx.z;
    const float* bias = (wsel == 0) ? bq : (wsel == 1) ? bk : bv;
    float* C32 = (wsel == 0) ? q : nullptr;
    __half* C16 = (wsel == 1) ? k16 : (wsel == 2) ? v16 : nullptr;
    mma_gemm_body(A, wt + (size_t)wsel * 65536, bias, C32, C16,
                  blockIdx.x * 128, blockIdx.y * 64);
}

__global__ __launch_bounds__(256, 2) void mma_o_kernel(
    const float* __restrict__ A, const __half* __restrict__ wt,
    const float* __restrict__ bias, float* __restrict__ C) {
    mma_gemm_body(A, wt + (size_t)3 * 65536, bias, C, nullptr,
                  blockIdx.x * 128, blockIdx.y * 64);
}

// ---------------------------------------------------------------------------
// Sparse masked attention (R4 structure; k/v fp16 -> half the traffic).
// Warp per (b,q), all 8 heads; lane owns 8 dims. Masked keys contribute
// exactly 0 (exp underflow) -> identical to the dense reference.
// ---------------------------------------------------------------------------
__global__ __launch_bounds__(256) void attn_kernel(
    const float* __restrict__ q, const __half* __restrict__ k,
    const __half* __restrict__ v, const unsigned* __restrict__ mask,
    float* __restrict__ att) {
    int gw   = blockIdx.x * 8 + (threadIdx.x >> 5);
    int lane = threadIdx.x & 31;
    int qi = gw & 511;
    int b  = gw >> 9;

    int off = lane * 8;
    size_t qrow = (size_t)gw * 256;
    float4 qa = *reinterpret_cast<const float4*>(q + qrow + off);
    float4 qb = *reinterpret_cast<const float4*>(q + qrow + off + 4);

    float m = -1e30f, l = 0.f;
    float acc[8];
#pragma unroll
    for (int d = 0; d < 8; d++) acc[d] = 0.f;

    const unsigned* mrow = mask + ((b << 9) + qi) * 16;
    size_t bbase = (size_t)(b << 9) * 256;

#pragma unroll 1
    for (int w = 0; w < 16; w++) {
        unsigned bits = mrow[w];
        while (bits) {
            int bit = __ffs(bits) - 1;
            bits &= bits - 1;
            int j = (w << 5) + bit;
            size_t rbase = bbase + (size_t)j * 256 + off;
            uint4 ku = *reinterpret_cast<const uint4*>(k + rbase);
            uint4 vu = *reinterpret_cast<const uint4*>(v + rbase);
            const __half2* kh = reinterpret_cast<const __half2*>(&ku);
            const __half2* vh = reinterpret_cast<const __half2*>(&vu);
            float2 k0 = __half22float2(kh[0]);
            float2 k1 = __half22float2(kh[1]);
            float2 k2 = __half22float2(kh[2]);
            float2 k3 = __half22float2(kh[3]);

            float s = qa.x * k0.x + qa.y * k0.y + qa.z * k1.x + qa.w * k1.y
                    + qb.x * k2.x + qb.y * k2.y + qb.z * k3.x + qb.w * k3.y;
            s += __shfl_xor_sync(0xffffffffu, s, 1);
            s += __shfl_xor_sync(0xffffffffu, s, 2);
            s *= SCALE;

            float mn   = fmaxf(m, s);
            float corr = __expf(m - mn);
            float p    = __expf(s - mn);
            l = l * corr + p;
            m = mn;
            float2 v0 = __half22float2(vh[0]);
            float2 v1 = __half22float2(vh[1]);
            float2 v2 = __half22float2(vh[2]);
            float2 v3 = __half22float2(vh[3]);
            acc[0] = acc[0] * corr + p * v0.x;
            acc[1] = acc[1] * corr + p * v0.y;
            acc[2] = acc[2] * corr + p * v1.x;
            acc[3] = acc[3] * corr + p * v1.y;
            acc[4] = acc[4] * corr + p * v2.x;
            acc[5] = acc[5] * corr + p * v2.y;
            acc[6] = acc[6] * corr + p * v3.x;
            acc[7] = acc[7] * corr + p * v3.y;
        }
    }

    float inv = 1.f / l;
    float4 oa, ob;
    oa.x = acc[0] * inv; oa.y = acc[1] * inv; oa.z = acc[2] * inv; oa.w = acc[3] * inv;
    ob.x = acc[4] * inv; ob.y = acc[5] * inv; ob.z = acc[6] * inv; ob.w = acc[7] * inv;
    *reinterpret_cast<float4*>(att + qrow + off)     = oa;
    *reinterpret_cast<float4*>(att + qrow + off + 4) = ob;
}

// ---------------------------------------------------------------------------
// Launch
// ---------------------------------------------------------------------------
extern "C" void kernel_launch(void* const* d_in, const int* in_sizes, int n_in,
                              void* d_out, int out_size) {
    const float* h   = (const float*)d_in[0];
    const int*   src = (const int*)d_in[1];
    const int*   dst = (const int*)d_in[2];
    const float* Wq  = (const float*)d_in[3];
    const float* bq  = (const float*)d_in[4];
    const float* Wk  = (const float*)d_in[5];
    const float* bk  = (const float*)d_in[6];
    const float* Wv  = (const float*)d_in[7];
    const float* bv  = (const float*)d_in[8];
    const float* Wo  = (const float*)d_in[9];
    const float* bo  = (const float*)d_in[10];
    float* out = (float*)d_out;

    float *pq, *patt;
    __half *pk16, *pv16, *pwt;
    unsigned* pmask;
    cudaGetSymbolAddress((void**)&pq,    g_q);
    cudaGetSymbolAddress((void**)&pk16,  g_k16);
    cudaGetSymbolAddress((void**)&pv16,  g_v16);
    cudaGetSymbolAddress((void**)&patt,  g_att);
    cudaGetSymbolAddress((void**)&pmask, g_mask);
    cudaGetSymbolAddress((void**)&pwt,   g_wt);

    // Weight transpose + fp16 convert; mask build (all independent)
    wconv_kernel<<<dim3(8, 8, 4), dim3(32, 8)>>>(Wq, Wk, Wv, Wo, pwt);
    mask_init_kernel<<<Bg * Ntok * 16 / 256, 256>>>(pmask);
    mask_edges_kernel<<<Eg / 256, 256>>>(src, dst, pmask);

    // Q/K/V projections (q fp32; k,v fp16 for the attention kernel)
    mma_qkv_kernel<<<dim3(MROWS / 128, 4, 3), 256>>>(
        h, pwt, bq, bk, bv, pq, pk16, pv16);

    // Sparse masked attention
    attn_kernel<<<MROWS / 8, 256>>>(pq, pk16, pv16, pmask, patt);

    // Output projection straight into d_out
    mma_o_kernel<<<dim3(MROWS / 128, 4), 256>>>(patt, pwt, bo, out);
}